// round 13
// baseline (speedup 1.0000x reference)
#include <cuda_runtime.h>
#include <cuda_fp16.h>

#define H 1024
#define W 1024
#define PLANE_SZ (H * W)

#define TX 128
#define TY 64
#define NT 512
#define ROWS (TY + 24)         // 88
#define RW 22                  // uint4 per row: 20 data + 2 guards
#define BUF_U4 (ROWS * RW)
#define PINF2 0x7C007C00u
#define ONE2  0x3C003C00u
#define NBLOCKS 1024

#define BST 5
#define BBUF (ROWS * BST)
#define BE_WORDS ((ROWS - 2) * BST)   // 430

__device__ double g_acc[6];
__device__ unsigned g_done;

// ---------------------------------------------------------------------------
__device__ __forceinline__ unsigned hmin2u(unsigned a, unsigned b) {
    __half2 r = __hmin2(*(__half2*)&a, *(__half2*)&b);
    return *(unsigned*)&r;
}
__device__ __forceinline__ unsigned hmax2u(unsigned a, unsigned b) {
    __half2 r = __hmax2(*(__half2*)&a, *(__half2*)&b);
    return *(unsigned*)&r;
}
__device__ __forceinline__ unsigned hsub2u(unsigned a, unsigned b) {
    __half2 r = __hsub2(*(__half2*)&a, *(__half2*)&b);
    return *(unsigned*)&r;
}
__device__ __forceinline__ unsigned hfma2u(unsigned a, unsigned b, unsigned c) {
    __half2 r = __hfma2(*(__half2*)&a, *(__half2*)&b, *(__half2*)&c);
    return *(unsigned*)&r;
}
__device__ __forceinline__ unsigned pack2(float a, float b) {
    __half2 h = __floats2half2_rn(a, b);
    return *(unsigned*)&h;
}
__device__ __forceinline__ float2 unpack2(unsigned v) {
    return __half22float2(*(__half2*)&v);
}
__device__ __forceinline__ unsigned remap2u(unsigned v) {
    unsigned m = __vcmpeq2(v, PINF2) & 0x80008000u;
    return v | m;
}
__device__ __forceinline__ unsigned xmask_f(int startpx) {
    unsigned m = ~0u;
    if (startpx < 0) { int k = -startpx; m = (k >= 32) ? 0u : (m << k); }
    int k2 = startpx + 32 - W;
    if (k2 > 0) m &= (k2 >= 32) ? 0u : (~0u >> k2);
    return m;
}

__device__ __forceinline__ float blockReduceSum(float v, float* red) {
    #pragma unroll
    for (int o = 16; o > 0; o >>= 1) v += __shfl_down_sync(0xffffffffu, v, o);
    int lane = threadIdx.x & 31;
    int wid  = threadIdx.x >> 5;
    if (lane == 0) red[wid] = v;
    __syncthreads();
    v = (threadIdx.x < 16) ? red[threadIdx.x] : 0.0f;
    if (wid == 0) {
        #pragma unroll
        for (int o = 8; o > 0; o >>= 1) v += __shfl_down_sync(0xffffffffu, v, o);
    }
    __syncthreads();
    return v;
}

// ---------------------------------------------------------------------------
template<bool BORDER>
__device__ __forceinline__ void erode_pass(const uint4* __restrict__ cur,
                                           uint4* __restrict__ nxt,
                                           int u1, int start, int end,
                                           bool xo0, bool xo1, bool xo2, bool xo3,
                                           int y0)
{
    const unsigned* cur32 = (const unsigned*)cur;
    int base = start * RW + u1;
    uint4 a = cur[base - RW];
    uint4 b = cur[base];
    for (int r = start; r < end; r++) {
        uint4 c = cur[base + RW];
        unsigned Lh = cur32[4 * base - 1];
        unsigned Rh = cur32[4 * base + 4];
        unsigned P0 = __byte_perm(Lh,  b.x, 0x5432);
        unsigned P1 = __byte_perm(b.x, b.y, 0x5432);
        unsigned P2 = __byte_perm(b.y, b.z, 0x5432);
        unsigned P3 = __byte_perm(b.z, b.w, 0x5432);
        unsigned P4 = __byte_perm(b.w, Rh, 0x5432);
        uint4 e;
        e.x = hmin2u(hmin2u(a.x, c.x), hmin2u(b.x, hmin2u(P0, P1)));
        e.y = hmin2u(hmin2u(a.y, c.y), hmin2u(b.y, hmin2u(P1, P2)));
        e.z = hmin2u(hmin2u(a.z, c.z), hmin2u(b.z, hmin2u(P2, P3)));
        e.w = hmin2u(hmin2u(a.w, c.w), hmin2u(b.w, hmin2u(P3, P4)));
        if (BORDER) {
            bool yo = ((unsigned)(y0 - 12 + r) >= H);
            if (xo0 | yo) e.x = PINF2;
            if (xo1 | yo) e.y = PINF2;
            if (xo2 | yo) e.z = PINF2;
            if (xo3 | yo) e.w = PINF2;
        }
        nxt[base] = e;
        a = b; b = c; base += RW;
    }
}

template<bool BORDER>
__device__ __forceinline__ uint4 rowmax_fn(const uint4* __restrict__ nxt,
                                           const unsigned* __restrict__ nxt32,
                                           int base)
{
    uint4 C = nxt[base];
    unsigned Lh = nxt32[4 * base - 1];
    unsigned Rh = nxt32[4 * base + 4];
    if (BORDER) {
        C.x = remap2u(C.x); C.y = remap2u(C.y); C.z = remap2u(C.z); C.w = remap2u(C.w);
        Lh = remap2u(Lh); Rh = remap2u(Rh);
    }
    unsigned P0 = __byte_perm(Lh,  C.x, 0x5432);
    unsigned P1 = __byte_perm(C.x, C.y, 0x5432);
    unsigned P2 = __byte_perm(C.y, C.z, 0x5432);
    unsigned P3 = __byte_perm(C.z, C.w, 0x5432);
    unsigned P4 = __byte_perm(C.w, Rh, 0x5432);
    uint4 h;
    h.x = hmax2u(C.x, hmax2u(P0, P1));
    h.y = hmax2u(C.y, hmax2u(P1, P2));
    h.z = hmax2u(C.z, hmax2u(P2, P3));
    h.w = hmax2u(C.w, hmax2u(P3, P4));
    return h;
}

template<bool BORDER>
__device__ __forceinline__ void dilate_skel(const uint4* __restrict__ av_buf,
                                            const uint4* __restrict__ dil,
                                            int u2, int yb, unsigned* uacc)
{
    const unsigned* dil32 = (const unsigned*)dil;
    uint4 h0 = rowmax_fn<BORDER>(dil, dil32, (yb - 1) * RW + u2);
    uint4 h1 = rowmax_fn<BORDER>(dil, dil32,  yb      * RW + u2);
    #pragma unroll
    for (int i = 0; i < 2; i++) {
        uint4 h2 = rowmax_fn<BORDER>(dil, dil32, (yb + 1 + i) * RW + u2);
        uint4 av = av_buf[(yb + i) * RW + u2];
        unsigned dw, nd;

        dw = hmax2u(h0.x, hmax2u(h1.x, h2.x));
        nd = hmin2u(hsub2u(dw, av.x), 0u);
        uacc[i*4+0] = hfma2u(uacc[i*4+0], nd, uacc[i*4+0]);

        dw = hmax2u(h0.y, hmax2u(h1.y, h2.y));
        nd = hmin2u(hsub2u(dw, av.y), 0u);
        uacc[i*4+1] = hfma2u(uacc[i*4+1], nd, uacc[i*4+1]);

        dw = hmax2u(h0.z, hmax2u(h1.z, h2.z));
        nd = hmin2u(hsub2u(dw, av.z), 0u);
        uacc[i*4+2] = hfma2u(uacc[i*4+2], nd, uacc[i*4+2]);

        dw = hmax2u(h0.w, hmax2u(h1.w, h2.w));
        nd = hmin2u(hsub2u(dw, av.w), 0u);
        uacc[i*4+3] = hfma2u(uacc[i*4+3], nd, uacc[i*4+3]);

        h0 = h1; h1 = h2;
    }
}

// ---------------------------------------------------------------------------
template<bool BORDER>
__device__ __forceinline__ void tile_run(const float* __restrict__ logits,
                                         const int* __restrict__ target,
                                         uint4* A, uint4* Bf, uint4* Cf,
                                         unsigned* T0, unsigned* T1, unsigned* T2,
                                         unsigned* SK,
                                         float* red, float* out)
{
    const int p8 = blockIdx.z;
    const int x0 = blockIdx.x * TX;
    const int y0 = blockIdx.y * TY;
    const int tid = threadIdx.x;
    const float* lg = logits + (size_t)p8 * PLANE_SZ;
    const int*   tp = target + (size_t)p8 * PLANE_SZ;

    if (tid < BBUF) {
        int r = tid / BST, w = tid - r * BST;
        unsigned V;
        if (BORDER) {
            int gy = y0 - 12 + r;
            V = ((unsigned)gy < H) ? xmask_f(x0 - 16 + 32 * w) : 0u;
        } else V = ~0u;
        T0[tid] = ~V;
    }
    __syncthreads();

    float s_inter = 0.f, s_cp = 0.f, s_ct = 0.f;
    for (int idx = tid; idx < BUF_U4; idx += NT) {
        int r = idx / RW;
        int u = idx - r * RW;
        uint4 vp;
        bool guard = (u == 0) | (u == RW - 1);
        if (!guard) {
            int gy = y0 - 12 + r;
            int gxb = x0 - 16 + 8 * (u - 1);
            bool rin = !BORDER || ((unsigned)gy < H);
            size_t rowoff = (size_t)gy * W;
            bool center = (u >= 3) & (u < 19) & (r >= 12) & (r < 12 + TY);
            unsigned tbits = 0;
            if (rin && (!BORDER || ((unsigned)gxb < W))) {
                float4 l = *(const float4*)(lg + rowoff + gxb);
                int4   t = *(const int4*)(tp + rowoff + gxb);
                float p0 = 1.0f / (1.0f + __expf(-l.x));
                float p1 = 1.0f / (1.0f + __expf(-l.y));
                float p2 = 1.0f / (1.0f + __expf(-l.z));
                float p3 = 1.0f / (1.0f + __expf(-l.w));
                vp.x = pack2(p0, p1); vp.y = pack2(p2, p3);
                tbits |= (unsigned)t.x | ((unsigned)t.y << 1) |
                         ((unsigned)t.z << 2) | ((unsigned)t.w << 3);
                if (center) {
                    s_inter += p0*(float)t.x + p1*(float)t.y + p2*(float)t.z + p3*(float)t.w;
                    s_cp += p0 + p1 + p2 + p3;
                    s_ct += (float)(t.x + t.y + t.z + t.w);
                }
            } else { vp.x = vp.y = PINF2; }
            if (rin && (!BORDER || ((unsigned)(gxb + 4) < W))) {
                float4 l = *(const float4*)(lg + rowoff + gxb + 4);
                int4   t = *(const int4*)(tp + rowoff + gxb + 4);
                float p0 = 1.0f / (1.0f + __expf(-l.x));
                float p1 = 1.0f / (1.0f + __expf(-l.y));
                float p2 = 1.0f / (1.0f + __expf(-l.z));
                float p3 = 1.0f / (1.0f + __expf(-l.w));
                vp.z = pack2(p0, p1); vp.w = pack2(p2, p3);
                tbits |= ((unsigned)t.x << 4) | ((unsigned)t.y << 5) |
                         ((unsigned)t.z << 6) | ((unsigned)t.w << 7);
                if (center) {
                    s_inter += p0*(float)t.x + p1*(float)t.y + p2*(float)t.z + p3*(float)t.w;
                    s_cp += p0 + p1 + p2 + p3;
                    s_ct += (float)(t.x + t.y + t.z + t.w);
                }
            } else { vp.z = vp.w = PINF2; }
            if (tbits) {
                int du = u - 1;
                atomicOr(&T0[r * BST + (du >> 2)], tbits << ((du & 3) * 8));
            }
        } else {
            vp = make_uint4(PINF2, PINF2, PINF2, PINF2);
            Bf[idx] = vp;
        }
        A[idx] = vp;
    }
    __syncthreads();

    // ---- fp16 erode mapping: 20 cols x 22 groups, rows split dynamically
    const int u1 = 1 + tid % 20;
    const int g1 = tid / 20;
    const bool g1ok = g1 < 22;
    bool xo0 = false, xo1 = false, xo2 = false, xo3 = false;
    if (BORDER) {
        int xb = x0 - 16 + 8 * (u1 - 1);
        xo0 = (unsigned)(xb + 0) >= W;
        xo1 = (unsigned)(xb + 2) >= W;
        xo2 = (unsigned)(xb + 4) >= W;
        xo3 = (unsigned)(xb + 6) >= W;
    }

    // ---- bit-erode role: threads 440..511 own all bit-erode words
    const bool ber_role = tid >= 440;
    const int bt = tid - 440;

    // ---- fp16 dilate mapping: 16 cols x 32 groups x 2 rows (all 512)
    const int u2 = 3 + (tid & 15);
    const int yb = 12 + 2 * (tid >> 4);

    // ---- bit dilate mapping: rows 12..75 x 5 words (320 active, scalar skw)
    const bool bd_act = tid < TY * BST;
    const int dr = 12 + tid / BST;
    const int dw2 = tid % BST;
    const int didx = dr * BST + dw2;
    unsigned m0 = ~0u, mm1 = ~0u, mp1 = ~0u;
    bool upok = true, dnok = true;
    if (BORDER && bd_act) {
        m0  = xmask_f(x0 - 16 + 32 * dw2);
        mm1 = (dw2 > 0) ? xmask_f(x0 - 16 + 32 * (dw2 - 1)) : 0u;
        mp1 = (dw2 < 4) ? xmask_f(x0 - 16 + 32 * (dw2 + 1)) : 0u;
        int gy = y0 - 12 + dr;
        upok = (gy - 1) >= 0;
        dnok = (gy + 1) < H;
    }
    unsigned skw = 0;

    unsigned uacc[8];
    #pragma unroll
    for (int i = 0; i < 8; i++) uacc[i] = ONE2;

    uint4    *pF = Cf, *cF = A,  *nF = Bf;
    unsigned *pT = T2, *cT = T0, *nT = T1;

    for (int k = 0; k <= 11; k++) {
        if (k > 0) {
            dilate_skel<BORDER>(pF, cF, u2, yb, uacc);
            if (bd_act) {
                unsigned d = 0;
                #pragma unroll
                for (int rr = -1; rr <= 1; rr++) {
                    bool ok = (rr == -1) ? upok : ((rr == 1) ? dnok : true);
                    int bse = (dr + rr) * BST + dw2;
                    unsigned c  = cT[bse] & m0;
                    unsigned l  = (dw2 > 0) ? (cT[bse - 1] & mm1) : 0u;
                    unsigned rt = (dw2 < 4) ? (cT[bse + 1] & mp1) : 0u;
                    unsigned rowv = c | ((c << 1) | (l >> 31)) | ((c >> 1) | (rt << 31));
                    if (BORDER && !ok) rowv = 0u;
                    d |= rowv;
                }
                unsigned ecur = pT[didx] & m0;
                skw |= ecur & ~d;
            }
        }
        if (k < 11) {
            const int m = 11 - k;
            if (ber_role) {
                // bit erode: 6 words per thread, all of [1, ROWS-1) x 5 words
                #pragma unroll
                for (int e = 0; e < 6; e++) {
                    int w = bt * 6 + e;
                    if (w < BE_WORDS) {
                        int br = 1 + w / BST;
                        int bw = w % BST;
                        int bidx = br * BST + bw;
                        unsigned xc = cT[bidx];
                        unsigned xu = cT[bidx - BST];
                        unsigned xd = cT[bidx + BST];
                        unsigned xl = (bw > 0) ? cT[bidx - 1] : ~0u;
                        unsigned xr = (bw < 4) ? cT[bidx + 1] : ~0u;
                        unsigned L = (xc << 1) | (xl >> 31);
                        unsigned R = (xc >> 1) | (xr << 31);
                        unsigned ev = xc & xu & xd & L & R;
                        if (BORDER) {
                            int gy = y0 - 12 + br;
                            unsigned V = ((unsigned)gy < H) ? xmask_f(x0 - 16 + 32 * bw) : 0u;
                            ev |= ~V;
                        }
                        nT[bidx] = ev;
                    }
                }
            } else {
                // fp16 erode: rows [lo,hi) split evenly over 22 groups
                const int lo = 12 - m, hi = 12 + TY + m;
                const int R  = hi - lo;
                int start = lo + (R * g1) / 22;
                int end   = lo + (R * (g1 + 1)) / 22;
                bool colact = (8 * (u1 - 1) < 144 + m) && (8 * u1 > 16 - m);
                if (g1ok && colact && start < end)
                    erode_pass<BORDER>(cF, nF, u1, start, end, xo0, xo1, xo2, xo3, y0);
            }
        }
        __syncthreads();
        uint4* t4; t4 = pF; pF = cF; cF = nF; nF = t4;
        unsigned* tb; tb = pT; pT = cT; cT = nT; nT = tb;
    }

    float s_st = 0.f;
    if (bd_act) {
        SK[didx] = skw;
        unsigned cmask = (dw2 == 0) ? 0xFFFF0000u : ((dw2 == 4) ? 0x0000FFFFu : ~0u);
        s_st = (float)__popc(skw & cmask);
    }
    __syncthreads();

    float sot = 0.f, so = 0.f;
    {
        const int du = u2 - 1;
        const int wd = du >> 2;
        const int bp = (du & 3) * 8;
        #pragma unroll
        for (int i = 0; i < 2; i++) {
            unsigned bbyte = (SK[(yb + i) * BST + wd] >> bp) & 0xffu;
            #pragma unroll
            for (int j = 0; j < 4; j++) {
                float2 f = unpack2(uacc[i * 4 + j]);
                float sx = 1.0f - f.x;
                float sy = 1.0f - f.y;
                so += sx + sy;
                if ((bbyte >> (2 * j)) & 1u)     sot += sx;
                if ((bbyte >> (2 * j + 1)) & 1u) sot += sy;
            }
        }
    }

    float b;
    b = blockReduceSum(s_inter, red);      if (tid == 0) atomicAdd(&g_acc[0], (double)b);
    b = blockReduceSum(s_cp + s_ct, red);  if (tid == 0) atomicAdd(&g_acc[1], (double)b);
    b = blockReduceSum(s_ct, red);         if (tid == 0) atomicAdd(&g_acc[2], (double)b);
    b = blockReduceSum(sot, red);          if (tid == 0) atomicAdd(&g_acc[3], (double)b);
    b = blockReduceSum(so,  red);          if (tid == 0) atomicAdd(&g_acc[4], (double)b);
    b = blockReduceSum(s_st, red);         if (tid == 0) atomicAdd(&g_acc[5], (double)b);

    if (tid == 0) {
        __threadfence();
        unsigned done = atomicAdd(&g_done, 1u);
        if (done == NBLOCKS - 1) {
            double inter = atomicAdd(&g_acc[0], 0.0);
            double card  = atomicAdd(&g_acc[1], 0.0);
            double sumt  = atomicAdd(&g_acc[2], 0.0);
            double sot2  = atomicAdd(&g_acc[3], 0.0);
            double so2   = atomicAdd(&g_acc[4], 0.0);
            double stk   = atomicAdd(&g_acc[5], 0.0);
            double score = (2.0 * inter + 1.0) / fmax(card + 1.0, 1e-7);
            double dice  = (1.0 - score) * (sumt > 0.0 ? 1.0 : 0.0);
            double tprec = (sot2 + 1.0) / (so2 + 1.0);
            double tsens = (sot2 + 1.0) / (stk + 1.0);
            double cs    = 2.0 * (tprec * tsens) / (tprec + tsens);
            double cl    = (1.0 - cs) * (stk > 0.0 ? 1.0 : 0.0);
            out[0] = (float)(0.5 * dice + 0.5 * cl);
            g_acc[0] = 0.0; g_acc[1] = 0.0; g_acc[2] = 0.0;
            g_acc[3] = 0.0; g_acc[4] = 0.0; g_acc[5] = 0.0;
            __threadfence();
            g_done = 0;
        }
    }
}

// ---------------------------------------------------------------------------
__global__ void __launch_bounds__(NT, 2)
fused_kernel(const float* __restrict__ logits, const int* __restrict__ target,
             float* __restrict__ out)
{
    extern __shared__ uint4 smem4[];
    __shared__ float red[32];
    uint4* A  = smem4;
    uint4* Bf = A + BUF_U4;
    uint4* Cf = Bf + BUF_U4;
    unsigned* bits = (unsigned*)(Cf + BUF_U4);
    unsigned* T0 = bits;
    unsigned* T1 = bits + BBUF;
    unsigned* T2 = bits + 2 * BBUF;
    unsigned* SK = bits + 3 * BBUF;
    bool border = (blockIdx.x == 0) | (blockIdx.x == gridDim.x - 1) |
                  (blockIdx.y == 0) | (blockIdx.y == gridDim.y - 1);
    if (border) tile_run<true >(logits, target, A, Bf, Cf, T0, T1, T2, SK, red, out);
    else        tile_run<false>(logits, target, A, Bf, Cf, T0, T1, T2, SK, red, out);
}

// ---------------------------------------------------------------------------
extern "C" void kernel_launch(void* const* d_in, const int* in_sizes, int n_in,
                              void* d_out, int out_size) {
    (void)in_sizes; (void)n_in; (void)out_size;
    const float* logits = (const float*)d_in[0];
    const int*   target = (const int*)d_in[1];

    const int smem_bytes = 3 * BUF_U4 * (int)sizeof(uint4) + 4 * BBUF * (int)sizeof(unsigned);
    cudaFuncSetAttribute(fused_kernel,
                         cudaFuncAttributeMaxDynamicSharedMemorySize, smem_bytes);

    dim3 grid(W / TX, H / TY, 8);
    fused_kernel<<<grid, NT, smem_bytes>>>(logits, target, (float*)d_out);
}

// round 14
// speedup vs baseline: 1.0737x; 1.0737x over previous
#include <cuda_runtime.h>
#include <cuda_fp16.h>

#define H 1024
#define W 1024
#define PLANE_SZ (H * W)

#define TX 128
#define TY 64
#define NT 512
#define ROWS (TY + 24)         // 88
#define RW 22                  // uint4 per row: 20 data + 2 guards
#define BUF_U4 (ROWS * RW)
#define PINF2 0x7C007C00u
#define ONE2  0x3C003C00u
#define NBLOCKS 1024

#define BST 5
#define BBUF (ROWS * BST)

__device__ double g_acc[6];
__device__ unsigned g_done;

// ---------------------------------------------------------------------------
__device__ __forceinline__ unsigned hmin2u(unsigned a, unsigned b) {
    __half2 r = __hmin2(*(__half2*)&a, *(__half2*)&b);
    return *(unsigned*)&r;
}
__device__ __forceinline__ unsigned hmax2u(unsigned a, unsigned b) {
    __half2 r = __hmax2(*(__half2*)&a, *(__half2*)&b);
    return *(unsigned*)&r;
}
__device__ __forceinline__ unsigned hsub2u(unsigned a, unsigned b) {
    __half2 r = __hsub2(*(__half2*)&a, *(__half2*)&b);
    return *(unsigned*)&r;
}
__device__ __forceinline__ unsigned hfma2u(unsigned a, unsigned b, unsigned c) {
    __half2 r = __hfma2(*(__half2*)&a, *(__half2*)&b, *(__half2*)&c);
    return *(unsigned*)&r;
}
__device__ __forceinline__ unsigned pack2(float a, float b) {
    __half2 h = __floats2half2_rn(a, b);
    return *(unsigned*)&h;
}
__device__ __forceinline__ float2 unpack2(unsigned v) {
    return __half22float2(*(__half2*)&v);
}
__device__ __forceinline__ unsigned remap2u(unsigned v) {
    unsigned m = __vcmpeq2(v, PINF2) & 0x80008000u;
    return v | m;
}
__device__ __forceinline__ unsigned xmask_f(int startpx) {
    unsigned m = ~0u;
    if (startpx < 0) { int k = -startpx; m = (k >= 32) ? 0u : (m << k); }
    int k2 = startpx + 32 - W;
    if (k2 > 0) m &= (k2 >= 32) ? 0u : (~0u >> k2);
    return m;
}

__device__ __forceinline__ float blockReduceSum(float v, float* red) {
    #pragma unroll
    for (int o = 16; o > 0; o >>= 1) v += __shfl_down_sync(0xffffffffu, v, o);
    int lane = threadIdx.x & 31;
    int wid  = threadIdx.x >> 5;
    if (lane == 0) red[wid] = v;
    __syncthreads();
    v = (threadIdx.x < 16) ? red[threadIdx.x] : 0.0f;
    if (wid == 0) {
        #pragma unroll
        for (int o = 8; o > 0; o >>= 1) v += __shfl_down_sync(0xffffffffu, v, o);
    }
    __syncthreads();
    return v;
}

// ---------------------------------------------------------------------------
template<bool BORDER>
__device__ __forceinline__ void erode_pass(const uint4* __restrict__ cur,
                                           uint4* __restrict__ nxt,
                                           int u1, int start, int end,
                                           bool xo0, bool xo1, bool xo2, bool xo3,
                                           int y0)
{
    const unsigned* cur32 = (const unsigned*)cur;
    int base = start * RW + u1;
    uint4 a = cur[base - RW];
    uint4 b = cur[base];
    for (int r = start; r < end; r++) {
        uint4 c = cur[base + RW];
        unsigned Lh = cur32[4 * base - 1];
        unsigned Rh = cur32[4 * base + 4];
        unsigned P0 = __byte_perm(Lh,  b.x, 0x5432);
        unsigned P1 = __byte_perm(b.x, b.y, 0x5432);
        unsigned P2 = __byte_perm(b.y, b.z, 0x5432);
        unsigned P3 = __byte_perm(b.z, b.w, 0x5432);
        unsigned P4 = __byte_perm(b.w, Rh, 0x5432);
        uint4 e;
        e.x = hmin2u(hmin2u(a.x, c.x), hmin2u(b.x, hmin2u(P0, P1)));
        e.y = hmin2u(hmin2u(a.y, c.y), hmin2u(b.y, hmin2u(P1, P2)));
        e.z = hmin2u(hmin2u(a.z, c.z), hmin2u(b.z, hmin2u(P2, P3)));
        e.w = hmin2u(hmin2u(a.w, c.w), hmin2u(b.w, hmin2u(P3, P4)));
        if (BORDER) {
            bool yo = ((unsigned)(y0 - 12 + r) >= H);
            if (xo0 | yo) e.x = PINF2;
            if (xo1 | yo) e.y = PINF2;
            if (xo2 | yo) e.z = PINF2;
            if (xo3 | yo) e.w = PINF2;
        }
        nxt[base] = e;
        a = b; b = c; base += RW;
    }
}

// Vertical-first dilate: v = 3-row max (pure HMAX2), then ONE horizontal
// 3-max per output row. Exact (max reordering), fewer PRMT/HMAX than
// horizontal-first rowmax.
template<bool BORDER>
__device__ __forceinline__ void dilate_skel(const uint4* __restrict__ av_buf,
                                            const uint4* __restrict__ dil,
                                            int u2, int yb, unsigned* uacc)
{
    const unsigned* dil32 = (const unsigned*)dil;
    uint4 c[4]; unsigned lh[4], rh[4];
    #pragma unroll
    for (int r = 0; r < 4; r++) {
        int base = (yb - 1 + r) * RW + u2;
        c[r] = dil[base];
        lh[r] = dil32[4 * base - 1];
        rh[r] = dil32[4 * base + 4];
        if (BORDER) {
            c[r].x = remap2u(c[r].x); c[r].y = remap2u(c[r].y);
            c[r].z = remap2u(c[r].z); c[r].w = remap2u(c[r].w);
            lh[r] = remap2u(lh[r]);   rh[r] = remap2u(rh[r]);
        }
    }
    #pragma unroll
    for (int i = 0; i < 2; i++) {
        uint4 v;
        v.x = hmax2u(c[i].x, hmax2u(c[i+1].x, c[i+2].x));
        v.y = hmax2u(c[i].y, hmax2u(c[i+1].y, c[i+2].y));
        v.z = hmax2u(c[i].z, hmax2u(c[i+1].z, c[i+2].z));
        v.w = hmax2u(c[i].w, hmax2u(c[i+1].w, c[i+2].w));
        unsigned vL = hmax2u(lh[i], hmax2u(lh[i+1], lh[i+2]));
        unsigned vR = hmax2u(rh[i], hmax2u(rh[i+1], rh[i+2]));
        unsigned P0 = __byte_perm(vL,  v.x, 0x5432);
        unsigned P1 = __byte_perm(v.x, v.y, 0x5432);
        unsigned P2 = __byte_perm(v.y, v.z, 0x5432);
        unsigned P3 = __byte_perm(v.z, v.w, 0x5432);
        unsigned P4 = __byte_perm(v.w, vR, 0x5432);
        uint4 av = av_buf[(yb + i) * RW + u2];
        unsigned dw, nd;

        dw = hmax2u(v.x, hmax2u(P0, P1));
        nd = hmin2u(hsub2u(dw, av.x), 0u);
        uacc[i*4+0] = hfma2u(uacc[i*4+0], nd, uacc[i*4+0]);

        dw = hmax2u(v.y, hmax2u(P1, P2));
        nd = hmin2u(hsub2u(dw, av.y), 0u);
        uacc[i*4+1] = hfma2u(uacc[i*4+1], nd, uacc[i*4+1]);

        dw = hmax2u(v.z, hmax2u(P2, P3));
        nd = hmin2u(hsub2u(dw, av.z), 0u);
        uacc[i*4+2] = hfma2u(uacc[i*4+2], nd, uacc[i*4+2]);

        dw = hmax2u(v.w, hmax2u(P3, P4));
        nd = hmin2u(hsub2u(dw, av.w), 0u);
        uacc[i*4+3] = hfma2u(uacc[i*4+3], nd, uacc[i*4+3]);
    }
}

// ---------------------------------------------------------------------------
template<bool BORDER>
__device__ __forceinline__ void tile_run(const float* __restrict__ logits,
                                         const int* __restrict__ target,
                                         uint4* A, uint4* Bf, uint4* Cf,
                                         unsigned* T0, unsigned* T1, unsigned* T2,
                                         unsigned* SK,
                                         float* red, float* out)
{
    const int p8 = blockIdx.z;
    const int x0 = blockIdx.x * TX;
    const int y0 = blockIdx.y * TY;
    const int tid = threadIdx.x;
    const float* lg = logits + (size_t)p8 * PLANE_SZ;
    const int*   tp = target + (size_t)p8 * PLANE_SZ;

    if (tid < BBUF) {
        int r = tid / BST, w = tid - r * BST;
        unsigned V;
        if (BORDER) {
            int gy = y0 - 12 + r;
            V = ((unsigned)gy < H) ? xmask_f(x0 - 16 + 32 * w) : 0u;
        } else V = ~0u;
        T0[tid] = ~V;
    }
    __syncthreads();

    float s_inter = 0.f, s_cp = 0.f, s_ct = 0.f;
    for (int idx = tid; idx < BUF_U4; idx += NT) {
        int r = idx / RW;
        int u = idx - r * RW;
        uint4 vp;
        bool guard = (u == 0) | (u == RW - 1);
        if (!guard) {
            int gy = y0 - 12 + r;
            int gxb = x0 - 16 + 8 * (u - 1);
            bool rin = !BORDER || ((unsigned)gy < H);
            size_t rowoff = (size_t)gy * W;
            bool center = (u >= 3) & (u < 19) & (r >= 12) & (r < 12 + TY);
            unsigned tbits = 0;
            if (rin && (!BORDER || ((unsigned)gxb < W))) {
                float4 l = *(const float4*)(lg + rowoff + gxb);
                int4   t = *(const int4*)(tp + rowoff + gxb);
                float p0 = 1.0f / (1.0f + __expf(-l.x));
                float p1 = 1.0f / (1.0f + __expf(-l.y));
                float p2 = 1.0f / (1.0f + __expf(-l.z));
                float p3 = 1.0f / (1.0f + __expf(-l.w));
                vp.x = pack2(p0, p1); vp.y = pack2(p2, p3);
                tbits |= (unsigned)t.x | ((unsigned)t.y << 1) |
                         ((unsigned)t.z << 2) | ((unsigned)t.w << 3);
                if (center) {
                    s_inter += p0*(float)t.x + p1*(float)t.y + p2*(float)t.z + p3*(float)t.w;
                    s_cp += p0 + p1 + p2 + p3;
                    s_ct += (float)(t.x + t.y + t.z + t.w);
                }
            } else { vp.x = vp.y = PINF2; }
            if (rin && (!BORDER || ((unsigned)(gxb + 4) < W))) {
                float4 l = *(const float4*)(lg + rowoff + gxb + 4);
                int4   t = *(const int4*)(tp + rowoff + gxb + 4);
                float p0 = 1.0f / (1.0f + __expf(-l.x));
                float p1 = 1.0f / (1.0f + __expf(-l.y));
                float p2 = 1.0f / (1.0f + __expf(-l.z));
                float p3 = 1.0f / (1.0f + __expf(-l.w));
                vp.z = pack2(p0, p1); vp.w = pack2(p2, p3);
                tbits |= ((unsigned)t.x << 4) | ((unsigned)t.y << 5) |
                         ((unsigned)t.z << 6) | ((unsigned)t.w << 7);
                if (center) {
                    s_inter += p0*(float)t.x + p1*(float)t.y + p2*(float)t.z + p3*(float)t.w;
                    s_cp += p0 + p1 + p2 + p3;
                    s_ct += (float)(t.x + t.y + t.z + t.w);
                }
            } else { vp.z = vp.w = PINF2; }
            if (tbits) {
                int du = u - 1;
                atomicOr(&T0[r * BST + (du >> 2)], tbits << ((du & 3) * 8));
            }
        } else {
            vp = make_uint4(PINF2, PINF2, PINF2, PINF2);
            Bf[idx] = vp;
        }
        A[idx] = vp;
    }
    __syncthreads();

    const int u1 = 1 + tid % 20;
    const int g1 = tid / 20;
    const int rs4 = 1 + 4 * g1;
    const bool g1ok = g1 < 22;
    bool xo0 = false, xo1 = false, xo2 = false, xo3 = false;
    if (BORDER) {
        int xb = x0 - 16 + 8 * (u1 - 1);
        xo0 = (unsigned)(xb + 0) >= W;
        xo1 = (unsigned)(xb + 2) >= W;
        xo2 = (unsigned)(xb + 4) >= W;
        xo3 = (unsigned)(xb + 6) >= W;
    }

    const bool be_act = tid < (ROWS - 2) * BST;
    const int br = 1 + tid / BST;
    const int bw = tid % BST;
    const int bidx = br * BST + bw;
    unsigned be_nv = 0;
    if (BORDER && be_act) {
        int gy = y0 - 12 + br;
        unsigned V = ((unsigned)gy < H) ? xmask_f(x0 - 16 + 32 * bw) : 0u;
        be_nv = ~V;
    }

    const int u2 = 3 + (tid & 15);
    const int yb = 12 + 2 * (tid >> 4);

    const bool bd_act = tid < TY * BST;
    const int dr = 12 + tid / BST;
    const int dw2 = tid % BST;
    const int didx = dr * BST + dw2;
    unsigned m0 = ~0u, mm1 = ~0u, mp1 = ~0u;
    bool upok = true, dnok = true;
    if (BORDER && bd_act) {
        m0  = xmask_f(x0 - 16 + 32 * dw2);
        mm1 = (dw2 > 0) ? xmask_f(x0 - 16 + 32 * (dw2 - 1)) : 0u;
        mp1 = (dw2 < 4) ? xmask_f(x0 - 16 + 32 * (dw2 + 1)) : 0u;
        int gy = y0 - 12 + dr;
        upok = (gy - 1) >= 0;
        dnok = (gy + 1) < H;
    }
    unsigned skw = 0;

    unsigned uacc[8];
    #pragma unroll
    for (int i = 0; i < 8; i++) uacc[i] = ONE2;

    uint4    *pF = Cf, *cF = A,  *nF = Bf;
    unsigned *pT = T2, *cT = T0, *nT = T1;

    for (int k = 0; k <= 11; k++) {
        if (k > 0) {
            dilate_skel<BORDER>(pF, cF, u2, yb, uacc);
            if (bd_act) {
                unsigned d = 0;
                #pragma unroll
                for (int rr = -1; rr <= 1; rr++) {
                    bool ok = (rr == -1) ? upok : ((rr == 1) ? dnok : true);
                    int bse = (dr + rr) * BST + dw2;
                    unsigned c  = cT[bse] & m0;
                    unsigned l  = (dw2 > 0) ? (cT[bse - 1] & mm1) : 0u;
                    unsigned rt = (dw2 < 4) ? (cT[bse + 1] & mp1) : 0u;
                    unsigned rowv = c | ((c << 1) | (l >> 31)) | ((c >> 1) | (rt << 31));
                    if (BORDER && !ok) rowv = 0u;
                    d |= rowv;
                }
                unsigned ecur = pT[didx] & m0;
                skw |= ecur & ~d;
            }
        }
        if (k < 11) {
            const int m = 11 - k;
            const int lo = 12 - m, hi = 12 + TY + m;
            int start = rs4 > lo ? rs4 : lo;
            int end   = (rs4 + 4 < hi) ? rs4 + 4 : hi;
            bool colact = (8 * (u1 - 1) < 144 + m) && (8 * u1 > 16 - m);
            if (g1ok && colact && start < end)
                erode_pass<BORDER>(cF, nF, u1, start, end, xo0, xo1, xo2, xo3, y0);
            if (be_act) {
                unsigned xc = cT[bidx];
                unsigned xu = cT[bidx - BST];
                unsigned xd = cT[bidx + BST];
                unsigned xl = (bw > 0) ? cT[bidx - 1] : ~0u;
                unsigned xr = (bw < 4) ? cT[bidx + 1] : ~0u;
                unsigned L = (xc << 1) | (xl >> 31);
                unsigned R = (xc >> 1) | (xr << 31);
                unsigned e = xc & xu & xd & L & R;
                if (BORDER) e |= be_nv;
                nT[bidx] = e;
            }
        }
        __syncthreads();
        uint4* t4; t4 = pF; pF = cF; cF = nF; nF = t4;
        unsigned* tb; tb = pT; pT = cT; cT = nT; nT = tb;
    }

    float s_st = 0.f;
    if (bd_act) {
        SK[didx] = skw;
        unsigned cmask = (dw2 == 0) ? 0xFFFF0000u : ((dw2 == 4) ? 0x0000FFFFu : ~0u);
        s_st = (float)__popc(skw & cmask);
    }
    __syncthreads();

    float sot = 0.f, so = 0.f;
    {
        const int du = u2 - 1;
        const int wd = du >> 2;
        const int bp = (du & 3) * 8;
        #pragma unroll
        for (int i = 0; i < 2; i++) {
            unsigned bbyte = (SK[(yb + i) * BST + wd] >> bp) & 0xffu;
            #pragma unroll
            for (int j = 0; j < 4; j++) {
                float2 f = unpack2(uacc[i * 4 + j]);
                float sx = 1.0f - f.x;
                float sy = 1.0f - f.y;
                so += sx + sy;
                if ((bbyte >> (2 * j)) & 1u)     sot += sx;
                if ((bbyte >> (2 * j + 1)) & 1u) sot += sy;
            }
        }
    }

    float b;
    b = blockReduceSum(s_inter, red);      if (tid == 0) atomicAdd(&g_acc[0], (double)b);
    b = blockReduceSum(s_cp + s_ct, red);  if (tid == 0) atomicAdd(&g_acc[1], (double)b);
    b = blockReduceSum(s_ct, red);         if (tid == 0) atomicAdd(&g_acc[2], (double)b);
    b = blockReduceSum(sot, red);          if (tid == 0) atomicAdd(&g_acc[3], (double)b);
    b = blockReduceSum(so,  red);          if (tid == 0) atomicAdd(&g_acc[4], (double)b);
    b = blockReduceSum(s_st, red);         if (tid == 0) atomicAdd(&g_acc[5], (double)b);

    if (tid == 0) {
        __threadfence();
        unsigned done = atomicAdd(&g_done, 1u);
        if (done == NBLOCKS - 1) {
            double inter = atomicAdd(&g_acc[0], 0.0);
            double card  = atomicAdd(&g_acc[1], 0.0);
            double sumt  = atomicAdd(&g_acc[2], 0.0);
            double sot2  = atomicAdd(&g_acc[3], 0.0);
            double so2   = atomicAdd(&g_acc[4], 0.0);
            double stk   = atomicAdd(&g_acc[5], 0.0);
            double score = (2.0 * inter + 1.0) / fmax(card + 1.0, 1e-7);
            double dice  = (1.0 - score) * (sumt > 0.0 ? 1.0 : 0.0);
            double tprec = (sot2 + 1.0) / (so2 + 1.0);
            double tsens = (sot2 + 1.0) / (stk + 1.0);
            double cs    = 2.0 * (tprec * tsens) / (tprec + tsens);
            double cl    = (1.0 - cs) * (stk > 0.0 ? 1.0 : 0.0);
            out[0] = (float)(0.5 * dice + 0.5 * cl);
            g_acc[0] = 0.0; g_acc[1] = 0.0; g_acc[2] = 0.0;
            g_acc[3] = 0.0; g_acc[4] = 0.0; g_acc[5] = 0.0;
            __threadfence();
            g_done = 0;
        }
    }
}

// ---------------------------------------------------------------------------
__global__ void __launch_bounds__(NT, 2)
fused_kernel(const float* __restrict__ logits, const int* __restrict__ target,
             float* __restrict__ out)
{
    extern __shared__ uint4 smem4[];
    __shared__ float red[32];
    uint4* A  = smem4;
    uint4* Bf = A + BUF_U4;
    uint4* Cf = Bf + BUF_U4;
    unsigned* bits = (unsigned*)(Cf + BUF_U4);
    unsigned* T0 = bits;
    unsigned* T1 = bits + BBUF;
    unsigned* T2 = bits + 2 * BBUF;
    unsigned* SK = bits + 3 * BBUF;
    bool border = (blockIdx.x == 0) | (blockIdx.x == gridDim.x - 1) |
                  (blockIdx.y == 0) | (blockIdx.y == gridDim.y - 1);
    if (border) tile_run<true >(logits, target, A, Bf, Cf, T0, T1, T2, SK, red, out);
    else        tile_run<false>(logits, target, A, Bf, Cf, T0, T1, T2, SK, red, out);
}

// ---------------------------------------------------------------------------
extern "C" void kernel_launch(void* const* d_in, const int* in_sizes, int n_in,
                              void* d_out, int out_size) {
    (void)in_sizes; (void)n_in; (void)out_size;
    const float* logits = (const float*)d_in[0];
    const int*   target = (const int*)d_in[1];

    const int smem_bytes = 3 * BUF_U4 * (int)sizeof(uint4) + 4 * BBUF * (int)sizeof(unsigned);
    cudaFuncSetAttribute(fused_kernel,
                         cudaFuncAttributeMaxDynamicSharedMemorySize, smem_bytes);

    dim3 grid(W / TX, H / TY, 8);
    fused_kernel<<<grid, NT, smem_bytes>>>(logits, target, (float*)d_out);
}

// round 15
// speedup vs baseline: 1.1146x; 1.0381x over previous
#include <cuda_runtime.h>
#include <cuda_fp16.h>

#define H 1024
#define W 1024
#define PLANE_SZ (H * W)

#define TX 128
#define TY 64
#define NT 512
#define ROWS (TY + 24)         // 88
#define RW 22                  // uint4 per row: 20 data + 2 guards
#define BUF_U4 (ROWS * RW)
#define PINF2 0x7C007C00u
#define ONE2  0x3C003C00u
#define NBLOCKS 1024

#define BST 5
#define BBUF (ROWS * BST)

__device__ double g_acc[6];
__device__ unsigned g_done;

// ---------------------------------------------------------------------------
__device__ __forceinline__ unsigned hmin2u(unsigned a, unsigned b) {
    __half2 r = __hmin2(*(__half2*)&a, *(__half2*)&b);
    return *(unsigned*)&r;
}
__device__ __forceinline__ unsigned hmax2u(unsigned a, unsigned b) {
    __half2 r = __hmax2(*(__half2*)&a, *(__half2*)&b);
    return *(unsigned*)&r;
}
__device__ __forceinline__ unsigned hsub2u(unsigned a, unsigned b) {
    __half2 r = __hsub2(*(__half2*)&a, *(__half2*)&b);
    return *(unsigned*)&r;
}
__device__ __forceinline__ unsigned hfma2u(unsigned a, unsigned b, unsigned c) {
    __half2 r = __hfma2(*(__half2*)&a, *(__half2*)&b, *(__half2*)&c);
    return *(unsigned*)&r;
}
__device__ __forceinline__ unsigned pack2(float a, float b) {
    __half2 h = __floats2half2_rn(a, b);
    return *(unsigned*)&h;
}
__device__ __forceinline__ float2 unpack2(unsigned v) {
    return __half22float2(*(__half2*)&v);
}
__device__ __forceinline__ unsigned remap2u(unsigned v) {
    unsigned m = __vcmpeq2(v, PINF2) & 0x80008000u;
    return v | m;
}
__device__ __forceinline__ unsigned xmask_f(int startpx) {
    unsigned m = ~0u;
    if (startpx < 0) { int k = -startpx; m = (k >= 32) ? 0u : (m << k); }
    int k2 = startpx + 32 - W;
    if (k2 > 0) m &= (k2 >= 32) ? 0u : (~0u >> k2);
    return m;
}

__device__ __forceinline__ float blockReduceSum(float v, float* red) {
    #pragma unroll
    for (int o = 16; o > 0; o >>= 1) v += __shfl_down_sync(0xffffffffu, v, o);
    int lane = threadIdx.x & 31;
    int wid  = threadIdx.x >> 5;
    if (lane == 0) red[wid] = v;
    __syncthreads();
    v = (threadIdx.x < 16) ? red[threadIdx.x] : 0.0f;
    if (wid == 0) {
        #pragma unroll
        for (int o = 8; o > 0; o >>= 1) v += __shfl_down_sync(0xffffffffu, v, o);
    }
    __syncthreads();
    return v;
}

// ---------------------------------------------------------------------------
template<bool BORDER>
__device__ __forceinline__ void erode_pass(const uint4* __restrict__ cur,
                                           uint4* __restrict__ nxt,
                                           int u1, int start, int end,
                                           bool xo0, bool xo1, bool xo2, bool xo3,
                                           int y0)
{
    const unsigned* cur32 = (const unsigned*)cur;
    int base = start * RW + u1;
    uint4 a = cur[base - RW];
    uint4 b = cur[base];
    for (int r = start; r < end; r++) {
        uint4 c = cur[base + RW];
        unsigned Lh = cur32[4 * base - 1];
        unsigned Rh = cur32[4 * base + 4];
        unsigned P0 = __byte_perm(Lh,  b.x, 0x5432);
        unsigned P1 = __byte_perm(b.x, b.y, 0x5432);
        unsigned P2 = __byte_perm(b.y, b.z, 0x5432);
        unsigned P3 = __byte_perm(b.z, b.w, 0x5432);
        unsigned P4 = __byte_perm(b.w, Rh, 0x5432);
        uint4 e;
        e.x = hmin2u(hmin2u(a.x, c.x), hmin2u(b.x, hmin2u(P0, P1)));
        e.y = hmin2u(hmin2u(a.y, c.y), hmin2u(b.y, hmin2u(P1, P2)));
        e.z = hmin2u(hmin2u(a.z, c.z), hmin2u(b.z, hmin2u(P2, P3)));
        e.w = hmin2u(hmin2u(a.w, c.w), hmin2u(b.w, hmin2u(P3, P4)));
        if (BORDER) {
            bool yo = ((unsigned)(y0 - 12 + r) >= H);
            if (xo0 | yo) e.x = PINF2;
            if (xo1 | yo) e.y = PINF2;
            if (xo2 | yo) e.z = PINF2;
            if (xo3 | yo) e.w = PINF2;
        }
        nxt[base] = e;
        a = b; b = c; base += RW;
    }
}

// Vertical-first dilate (R14): v = 3-row max, then ONE horizontal 3-max/row.
template<bool BORDER>
__device__ __forceinline__ void dilate_skel(const uint4* __restrict__ av_buf,
                                            const uint4* __restrict__ dil,
                                            int u2, int yb, unsigned* uacc)
{
    const unsigned* dil32 = (const unsigned*)dil;
    uint4 c[4]; unsigned lh[4], rh[4];
    #pragma unroll
    for (int r = 0; r < 4; r++) {
        int base = (yb - 1 + r) * RW + u2;
        c[r] = dil[base];
        lh[r] = dil32[4 * base - 1];
        rh[r] = dil32[4 * base + 4];
        if (BORDER) {
            c[r].x = remap2u(c[r].x); c[r].y = remap2u(c[r].y);
            c[r].z = remap2u(c[r].z); c[r].w = remap2u(c[r].w);
            lh[r] = remap2u(lh[r]);   rh[r] = remap2u(rh[r]);
        }
    }
    #pragma unroll
    for (int i = 0; i < 2; i++) {
        uint4 v;
        v.x = hmax2u(c[i].x, hmax2u(c[i+1].x, c[i+2].x));
        v.y = hmax2u(c[i].y, hmax2u(c[i+1].y, c[i+2].y));
        v.z = hmax2u(c[i].z, hmax2u(c[i+1].z, c[i+2].z));
        v.w = hmax2u(c[i].w, hmax2u(c[i+1].w, c[i+2].w));
        unsigned vL = hmax2u(lh[i], hmax2u(lh[i+1], lh[i+2]));
        unsigned vR = hmax2u(rh[i], hmax2u(rh[i+1], rh[i+2]));
        unsigned P0 = __byte_perm(vL,  v.x, 0x5432);
        unsigned P1 = __byte_perm(v.x, v.y, 0x5432);
        unsigned P2 = __byte_perm(v.y, v.z, 0x5432);
        unsigned P3 = __byte_perm(v.z, v.w, 0x5432);
        unsigned P4 = __byte_perm(v.w, vR, 0x5432);
        uint4 av = av_buf[(yb + i) * RW + u2];
        unsigned dw, nd;

        dw = hmax2u(v.x, hmax2u(P0, P1));
        nd = hmin2u(hsub2u(dw, av.x), 0u);
        uacc[i*4+0] = hfma2u(uacc[i*4+0], nd, uacc[i*4+0]);

        dw = hmax2u(v.y, hmax2u(P1, P2));
        nd = hmin2u(hsub2u(dw, av.y), 0u);
        uacc[i*4+1] = hfma2u(uacc[i*4+1], nd, uacc[i*4+1]);

        dw = hmax2u(v.z, hmax2u(P2, P3));
        nd = hmin2u(hsub2u(dw, av.z), 0u);
        uacc[i*4+2] = hfma2u(uacc[i*4+2], nd, uacc[i*4+2]);

        dw = hmax2u(v.w, hmax2u(P3, P4));
        nd = hmin2u(hsub2u(dw, av.w), 0u);
        uacc[i*4+3] = hfma2u(uacc[i*4+3], nd, uacc[i*4+3]);
    }
}

// ---------------------------------------------------------------------------
template<bool BORDER>
__device__ __forceinline__ void tile_run(const float* __restrict__ logits,
                                         const int* __restrict__ target,
                                         uint4* A, uint4* Bf, uint4* Cf,
                                         unsigned* T0, unsigned* T1, unsigned* T2,
                                         unsigned* SK,
                                         float* red, float* out)
{
    const int p8 = blockIdx.z;
    const int x0 = blockIdx.x * TX;
    const int y0 = blockIdx.y * TY;
    const int tid = threadIdx.x;
    const float* lg = logits + (size_t)p8 * PLANE_SZ;
    const int*   tp = target + (size_t)p8 * PLANE_SZ;

    if (tid < BBUF) {
        int r = tid / BST, w = tid - r * BST;
        unsigned V;
        if (BORDER) {
            int gy = y0 - 12 + r;
            V = ((unsigned)gy < H) ? xmask_f(x0 - 16 + 32 * w) : 0u;
        } else V = ~0u;
        T0[tid] = ~V;
    }
    __syncthreads();

    float s_inter = 0.f, s_cp = 0.f, s_ct = 0.f;
    for (int idx = tid; idx < BUF_U4; idx += NT) {
        int r = idx / RW;
        int u = idx - r * RW;
        uint4 vp;
        bool guard = (u == 0) | (u == RW - 1);
        if (!guard) {
            int gy = y0 - 12 + r;
            int gxb = x0 - 16 + 8 * (u - 1);
            bool rin = !BORDER || ((unsigned)gy < H);
            size_t rowoff = (size_t)gy * W;
            bool center = (u >= 3) & (u < 19) & (r >= 12) & (r < 12 + TY);
            unsigned tbits = 0;
            if (rin && (!BORDER || ((unsigned)gxb < W))) {
                float4 l = *(const float4*)(lg + rowoff + gxb);
                int4   t = *(const int4*)(tp + rowoff + gxb);
                float p0 = 1.0f / (1.0f + __expf(-l.x));
                float p1 = 1.0f / (1.0f + __expf(-l.y));
                float p2 = 1.0f / (1.0f + __expf(-l.z));
                float p3 = 1.0f / (1.0f + __expf(-l.w));
                vp.x = pack2(p0, p1); vp.y = pack2(p2, p3);
                tbits |= (unsigned)t.x | ((unsigned)t.y << 1) |
                         ((unsigned)t.z << 2) | ((unsigned)t.w << 3);
                if (center) {
                    s_inter += p0*(float)t.x + p1*(float)t.y + p2*(float)t.z + p3*(float)t.w;
                    s_cp += p0 + p1 + p2 + p3;
                    s_ct += (float)(t.x + t.y + t.z + t.w);
                }
            } else { vp.x = vp.y = PINF2; }
            if (rin && (!BORDER || ((unsigned)(gxb + 4) < W))) {
                float4 l = *(const float4*)(lg + rowoff + gxb + 4);
                int4   t = *(const int4*)(tp + rowoff + gxb + 4);
                float p0 = 1.0f / (1.0f + __expf(-l.x));
                float p1 = 1.0f / (1.0f + __expf(-l.y));
                float p2 = 1.0f / (1.0f + __expf(-l.z));
                float p3 = 1.0f / (1.0f + __expf(-l.w));
                vp.z = pack2(p0, p1); vp.w = pack2(p2, p3);
                tbits |= ((unsigned)t.x << 4) | ((unsigned)t.y << 5) |
                         ((unsigned)t.z << 6) | ((unsigned)t.w << 7);
                if (center) {
                    s_inter += p0*(float)t.x + p1*(float)t.y + p2*(float)t.z + p3*(float)t.w;
                    s_cp += p0 + p1 + p2 + p3;
                    s_ct += (float)(t.x + t.y + t.z + t.w);
                }
            } else { vp.z = vp.w = PINF2; }
            if (tbits) {
                int du = u - 1;
                atomicOr(&T0[r * BST + (du >> 2)], tbits << ((du & 3) * 8));
            }
        } else {
            vp = make_uint4(PINF2, PINF2, PINF2, PINF2);
            Bf[idx] = vp;
        }
        A[idx] = vp;
    }
    __syncthreads();

    // ---- fp16 erode mapping: 20 cols x 25 balanced row-groups
    const int u1 = 1 + tid % 20;
    const int g1 = tid / 20;          // 0..25 (group 25 provably idle)
    bool xo0 = false, xo1 = false, xo2 = false, xo3 = false;
    if (BORDER) {
        int xb = x0 - 16 + 8 * (u1 - 1);
        xo0 = (unsigned)(xb + 0) >= W;
        xo1 = (unsigned)(xb + 2) >= W;
        xo2 = (unsigned)(xb + 4) >= W;
        xo3 = (unsigned)(xb + 6) >= W;
    }

    const bool be_act = tid < (ROWS - 2) * BST;
    const int br = 1 + tid / BST;
    const int bw = tid % BST;
    const int bidx = br * BST + bw;
    unsigned be_nv = 0;
    if (BORDER && be_act) {
        int gy = y0 - 12 + br;
        unsigned V = ((unsigned)gy < H) ? xmask_f(x0 - 16 + 32 * bw) : 0u;
        be_nv = ~V;
    }

    const int u2 = 3 + (tid & 15);
    const int yb = 12 + 2 * (tid >> 4);

    const bool bd_act = tid < TY * BST;
    const int dr = 12 + tid / BST;
    const int dw2 = tid % BST;
    const int didx = dr * BST + dw2;
    unsigned m0 = ~0u, mm1 = ~0u, mp1 = ~0u;
    bool upok = true, dnok = true;
    if (BORDER && bd_act) {
        m0  = xmask_f(x0 - 16 + 32 * dw2);
        mm1 = (dw2 > 0) ? xmask_f(x0 - 16 + 32 * (dw2 - 1)) : 0u;
        mp1 = (dw2 < 4) ? xmask_f(x0 - 16 + 32 * (dw2 + 1)) : 0u;
        int gy = y0 - 12 + dr;
        upok = (gy - 1) >= 0;
        dnok = (gy + 1) < H;
    }
    unsigned skw = 0;

    unsigned uacc[8];
    #pragma unroll
    for (int i = 0; i < 8; i++) uacc[i] = ONE2;

    uint4    *pF = Cf, *cF = A,  *nF = Bf;
    unsigned *pT = T2, *cT = T0, *nT = T1;

    for (int k = 0; k <= 11; k++) {
        if (k > 0) {
            dilate_skel<BORDER>(pF, cF, u2, yb, uacc);
            if (bd_act) {
                unsigned d = 0;
                #pragma unroll
                for (int rr = -1; rr <= 1; rr++) {
                    bool ok = (rr == -1) ? upok : ((rr == 1) ? dnok : true);
                    int bse = (dr + rr) * BST + dw2;
                    unsigned c  = cT[bse] & m0;
                    unsigned l  = (dw2 > 0) ? (cT[bse - 1] & mm1) : 0u;
                    unsigned rt = (dw2 < 4) ? (cT[bse + 1] & mp1) : 0u;
                    unsigned rowv = c | ((c << 1) | (l >> 31)) | ((c >> 1) | (rt << 31));
                    if (BORDER && !ok) rowv = 0u;
                    d |= rowv;
                }
                unsigned ecur = pT[didx] & m0;
                skw |= ecur & ~d;
            }
        }
        if (k < 11) {
            const int m = 11 - k;
            const int lo = 12 - m, hi = 12 + TY + m;
            const int rows = hi - lo;              // 64 + 2m
            const int rg = (rows + 24) / 25;       // 3 or 4; 25*rg >= rows
            int start = lo + g1 * rg;
            int end   = start + rg;
            if (end > hi) end = hi;
            bool colact = (8 * (u1 - 1) < 144 + m) && (8 * u1 > 16 - m);
            if (colact && start < end)
                erode_pass<BORDER>(cF, nF, u1, start, end, xo0, xo1, xo2, xo3, y0);
            if (be_act) {
                unsigned xc = cT[bidx];
                unsigned xu = cT[bidx - BST];
                unsigned xd = cT[bidx + BST];
                unsigned xl = (bw > 0) ? cT[bidx - 1] : ~0u;
                unsigned xr = (bw < 4) ? cT[bidx + 1] : ~0u;
                unsigned L = (xc << 1) | (xl >> 31);
                unsigned R = (xc >> 1) | (xr << 31);
                unsigned e = xc & xu & xd & L & R;
                if (BORDER) e |= be_nv;
                nT[bidx] = e;
            }
        }
        __syncthreads();
        uint4* t4; t4 = pF; pF = cF; cF = nF; nF = t4;
        unsigned* tb; tb = pT; pT = cT; cT = nT; nT = tb;
    }

    float s_st = 0.f;
    if (bd_act) {
        SK[didx] = skw;
        unsigned cmask = (dw2 == 0) ? 0xFFFF0000u : ((dw2 == 4) ? 0x0000FFFFu : ~0u);
        s_st = (float)__popc(skw & cmask);
    }
    __syncthreads();

    float sot = 0.f, so = 0.f;
    {
        const int du = u2 - 1;
        const int wd = du >> 2;
        const int bp = (du & 3) * 8;
        #pragma unroll
        for (int i = 0; i < 2; i++) {
            unsigned bbyte = (SK[(yb + i) * BST + wd] >> bp) & 0xffu;
            #pragma unroll
            for (int j = 0; j < 4; j++) {
                float2 f = unpack2(uacc[i * 4 + j]);
                float sx = 1.0f - f.x;
                float sy = 1.0f - f.y;
                so += sx + sy;
                if ((bbyte >> (2 * j)) & 1u)     sot += sx;
                if ((bbyte >> (2 * j + 1)) & 1u) sot += sy;
            }
        }
    }

    float b;
    b = blockReduceSum(s_inter, red);      if (tid == 0) atomicAdd(&g_acc[0], (double)b);
    b = blockReduceSum(s_cp + s_ct, red);  if (tid == 0) atomicAdd(&g_acc[1], (double)b);
    b = blockReduceSum(s_ct, red);         if (tid == 0) atomicAdd(&g_acc[2], (double)b);
    b = blockReduceSum(sot, red);          if (tid == 0) atomicAdd(&g_acc[3], (double)b);
    b = blockReduceSum(so,  red);          if (tid == 0) atomicAdd(&g_acc[4], (double)b);
    b = blockReduceSum(s_st, red);         if (tid == 0) atomicAdd(&g_acc[5], (double)b);

    if (tid == 0) {
        __threadfence();
        unsigned done = atomicAdd(&g_done, 1u);
        if (done == NBLOCKS - 1) {
            double inter = atomicAdd(&g_acc[0], 0.0);
            double card  = atomicAdd(&g_acc[1], 0.0);
            double sumt  = atomicAdd(&g_acc[2], 0.0);
            double sot2  = atomicAdd(&g_acc[3], 0.0);
            double so2   = atomicAdd(&g_acc[4], 0.0);
            double stk   = atomicAdd(&g_acc[5], 0.0);
            double score = (2.0 * inter + 1.0) / fmax(card + 1.0, 1e-7);
            double dice  = (1.0 - score) * (sumt > 0.0 ? 1.0 : 0.0);
            double tprec = (sot2 + 1.0) / (so2 + 1.0);
            double tsens = (sot2 + 1.0) / (stk + 1.0);
            double cs    = 2.0 * (tprec * tsens) / (tprec + tsens);
            double cl    = (1.0 - cs) * (stk > 0.0 ? 1.0 : 0.0);
            out[0] = (float)(0.5 * dice + 0.5 * cl);
            g_acc[0] = 0.0; g_acc[1] = 0.0; g_acc[2] = 0.0;
            g_acc[3] = 0.0; g_acc[4] = 0.0; g_acc[5] = 0.0;
            __threadfence();
            g_done = 0;
        }
    }
}

// ---------------------------------------------------------------------------
__global__ void __launch_bounds__(NT, 2)
fused_kernel(const float* __restrict__ logits, const int* __restrict__ target,
             float* __restrict__ out)
{
    extern __shared__ uint4 smem4[];
    __shared__ float red[32];
    uint4* A  = smem4;
    uint4* Bf = A + BUF_U4;
    uint4* Cf = Bf + BUF_U4;
    unsigned* bits = (unsigned*)(Cf + BUF_U4);
    unsigned* T0 = bits;
    unsigned* T1 = bits + BBUF;
    unsigned* T2 = bits + 2 * BBUF;
    unsigned* SK = bits + 3 * BBUF;
    bool border = (blockIdx.x == 0) | (blockIdx.x == gridDim.x - 1) |
                  (blockIdx.y == 0) | (blockIdx.y == gridDim.y - 1);
    if (border) tile_run<true >(logits, target, A, Bf, Cf, T0, T1, T2, SK, red, out);
    else        tile_run<false>(logits, target, A, Bf, Cf, T0, T1, T2, SK, red, out);
}

// ---------------------------------------------------------------------------
extern "C" void kernel_launch(void* const* d_in, const int* in_sizes, int n_in,
                              void* d_out, int out_size) {
    (void)in_sizes; (void)n_in; (void)out_size;
    const float* logits = (const float*)d_in[0];
    const int*   target = (const int*)d_in[1];

    const int smem_bytes = 3 * BUF_U4 * (int)sizeof(uint4) + 4 * BBUF * (int)sizeof(unsigned);
    cudaFuncSetAttribute(fused_kernel,
                         cudaFuncAttributeMaxDynamicSharedMemorySize, smem_bytes);

    dim3 grid(W / TX, H / TY, 8);
    fused_kernel<<<grid, NT, smem_bytes>>>(logits, target, (float*)d_out);
}